// round 1
// baseline (speedup 1.0000x reference)
#include <cuda_runtime.h>
#include <math.h>

// Problem constants
#define SEQ   2048
#define DMODEL 1024
#define NH    16
#define NKV   4
#define HD    64
#define QDIM  (NH * HD)    // 1024
#define KVDIM (NKV * HD)   // 256

// Scratch (device globals — no allocation allowed in kernel_launch)
__device__ float g_Q[SEQ * QDIM];
__device__ float g_K[SEQ * KVDIM];
__device__ float g_V[SEQ * KVDIM];
__device__ float g_O[SEQ * QDIM];

// ---------------------------------------------------------------------------
// SGEMM: C[M,N] = A[M,K] * B[K,N], row-major. M%128==0, N%128==0, K%8==0.
// 128x128 block tile, 8x8 per-thread microtile, 256 threads.
// ---------------------------------------------------------------------------
__global__ __launch_bounds__(256)
void sgemm_kernel(const float* __restrict__ A, const float* __restrict__ B,
                  float* __restrict__ C, int M, int N, int K) {
    const int BM = 128, BN = 128, BK = 8, TM = 8, TN = 8;
    __shared__ float As[8][128];
    __shared__ float Bs[8][128];

    const int tid = threadIdx.x;
    const int tx = tid % (BN / TN);   // 0..15
    const int ty = tid / (BN / TN);   // 0..15
    const int row0 = blockIdx.y * BM;
    const int col0 = blockIdx.x * BN;

    float acc[TM][TN];
    #pragma unroll
    for (int i = 0; i < TM; i++)
        #pragma unroll
        for (int j = 0; j < TN; j++)
            acc[i][j] = 0.f;

    for (int k0 = 0; k0 < K; k0 += BK) {
        // Load A tile (128 x 8) transposed into As[k][m]
        #pragma unroll
        for (int i = tid; i < BM * BK; i += 256) {
            int r = i / BK, c = i % BK;
            As[c][r] = A[(size_t)(row0 + r) * K + k0 + c];
        }
        // Load B tile (8 x 128)
        #pragma unroll
        for (int i = tid; i < BK * BN; i += 256) {
            int r = i / BN, c = i % BN;
            Bs[r][c] = B[(size_t)(k0 + r) * N + col0 + c];
        }
        __syncthreads();

        #pragma unroll
        for (int kk = 0; kk < BK; kk++) {
            float a[TM], b[TN];
            #pragma unroll
            for (int i = 0; i < TM; i++) a[i] = As[kk][ty * TM + i];
            #pragma unroll
            for (int j = 0; j < TN; j++) b[j] = Bs[kk][tx * TN + j];
            #pragma unroll
            for (int i = 0; i < TM; i++)
                #pragma unroll
                for (int j = 0; j < TN; j++)
                    acc[i][j] = fmaf(a[i], b[j], acc[i][j]);
        }
        __syncthreads();
    }

    #pragma unroll
    for (int i = 0; i < TM; i++)
        #pragma unroll
        for (int j = 0; j < TN; j++)
            C[(size_t)(row0 + ty * TM + i) * N + col0 + tx * TN + j] = acc[i][j];
}

// ---------------------------------------------------------------------------
// RoPE (in place). T is [SEQ, nheads*HD]. cos/sin tables are [SEQ, HD/2].
// Pair (i, i+32): t1' = t1*c - t2*s ; t2' = t2*c + t1*s
// ---------------------------------------------------------------------------
__global__ void rope_kernel(float* __restrict__ T,
                            const float* __restrict__ cosT,
                            const float* __restrict__ sinT,
                            int nheads) {
    int idx = blockIdx.x * blockDim.x + threadIdx.x;
    int total = SEQ * nheads * (HD / 2);
    if (idx >= total) return;
    int i = idx % (HD / 2);
    int h = (idx / (HD / 2)) % nheads;
    int s = idx / ((HD / 2) * nheads);
    float c  = cosT[s * (HD / 2) + i];
    float sn = sinT[s * (HD / 2) + i];
    float* row = T + (size_t)s * nheads * HD + h * HD;
    float t1 = row[i];
    float t2 = row[i + HD / 2];
    row[i]          = t1 * c - t2 * sn;
    row[i + HD / 2] = t2 * c + t1 * sn;
}

// ---------------------------------------------------------------------------
// Flash-style causal attention with online softmax.
// Grid: (SEQ/BQ, NH). Block: BQ threads, one q-row per thread.
// Q: [SEQ, QDIM], K/V: [SEQ, KVDIM], O: [SEQ, QDIM].
// ---------------------------------------------------------------------------
#define BQ  64
#define BKT 32

__global__ __launch_bounds__(BQ)
void attn_kernel(const float* __restrict__ Q, const float* __restrict__ K,
                 const float* __restrict__ V, float* __restrict__ O) {
    const int qt  = blockIdx.x;
    const int h   = blockIdx.y;
    const int kvh = h / (NH / NKV);
    const int row = threadIdx.x;           // 0..BQ-1
    const int qg  = qt * BQ + row;         // global q position

    __shared__ float Qs[BQ][HD + 1];       // +1 pad: conflict-free Qs[row][d]
    __shared__ float Ks[BKT][HD];
    __shared__ float Vs[BKT][HD];

    // Load Q tile
    for (int i = threadIdx.x; i < BQ * HD; i += BQ) {
        int r = i / HD, d = i % HD;
        Qs[r][d] = Q[(size_t)(qt * BQ + r) * QDIM + h * HD + d];
    }

    float acc[HD];
    #pragma unroll
    for (int d = 0; d < HD; d++) acc[d] = 0.f;
    float m = -INFINITY;
    float l = 0.f;
    const float scale = 0.125f;            // 1/sqrt(64)

    const int nkt = ((qt + 1) * BQ) / BKT; // k-tiles covering causal range

    for (int t = 0; t < nkt; t++) {
        __syncthreads();
        // Load K/V tiles
        for (int i = threadIdx.x; i < BKT * HD; i += BQ) {
            int r = i / HD, d = i % HD;
            size_t gk = (size_t)(t * BKT + r) * KVDIM + kvh * HD + d;
            Ks[r][d] = K[gk];
            Vs[r][d] = V[gk];
        }
        __syncthreads();

        // Scores: sc[j] = Qs[row] . Ks[j]
        float sc[BKT];
        #pragma unroll
        for (int j = 0; j < BKT; j++) sc[j] = 0.f;
        #pragma unroll 4
        for (int d = 0; d < HD; d++) {
            float qv = Qs[row][d];
            #pragma unroll
            for (int j = 0; j < BKT; j++)
                sc[j] = fmaf(qv, Ks[j][d], sc[j]);
        }

        // Causal mask + tile max
        float mt = m;
        #pragma unroll
        for (int j = 0; j < BKT; j++) {
            int kg = t * BKT + j;
            sc[j] = (kg <= qg) ? sc[j] * scale : -INFINITY;
            mt = fmaxf(mt, sc[j]);
        }

        // Online softmax update
        float corr = __expf(m - mt);       // 0 on first tile (m = -inf)
        float psum = 0.f;
        #pragma unroll
        for (int j = 0; j < BKT; j++) {
            sc[j] = __expf(sc[j] - mt);    // reuse sc[] as p[]
            psum += sc[j];
        }
        l = l * corr + psum;
        m = mt;

        #pragma unroll
        for (int d = 0; d < HD; d++) acc[d] *= corr;
        for (int j = 0; j < BKT; j++) {
            float pj = sc[j];
            #pragma unroll
            for (int d = 0; d < HD; d++)
                acc[d] = fmaf(pj, Vs[j][d], acc[d]);
        }
    }

    float inv_l = 1.f / l;
    #pragma unroll
    for (int d = 0; d < HD; d++)
        O[(size_t)qg * QDIM + h * HD + d] = acc[d] * inv_l;
}

// ---------------------------------------------------------------------------
// Launch
// Inputs (metadata order): x, rope_cos, rope_sin, Wq, Wk, Wv, Wo
// ---------------------------------------------------------------------------
extern "C" void kernel_launch(void* const* d_in, const int* in_sizes, int n_in,
                              void* d_out, int out_size) {
    const float* x    = (const float*)d_in[0];
    const float* cosT = (const float*)d_in[1];
    const float* sinT = (const float*)d_in[2];
    const float* Wq   = (const float*)d_in[3];
    const float* Wk   = (const float*)d_in[4];
    const float* Wv   = (const float*)d_in[5];
    const float* Wo   = (const float*)d_in[6];
    float* out = (float*)d_out;

    float *Qp, *Kp, *Vp, *Op;
    cudaGetSymbolAddress((void**)&Qp, g_Q);
    cudaGetSymbolAddress((void**)&Kp, g_K);
    cudaGetSymbolAddress((void**)&Vp, g_V);
    cudaGetSymbolAddress((void**)&Op, g_O);

    // QKV projections
    {
        dim3 grid(QDIM / 128, SEQ / 128);
        sgemm_kernel<<<grid, 256>>>(x, Wq, Qp, SEQ, QDIM, DMODEL);
    }
    {
        dim3 grid(KVDIM / 128, SEQ / 128);
        sgemm_kernel<<<grid, 256>>>(x, Wk, Kp, SEQ, KVDIM, DMODEL);
        sgemm_kernel<<<grid, 256>>>(x, Wv, Vp, SEQ, KVDIM, DMODEL);
    }

    // RoPE on Q and K
    {
        int totq = SEQ * NH * (HD / 2);
        rope_kernel<<<(totq + 255) / 256, 256>>>(Qp, cosT, sinT, NH);
        int totk = SEQ * NKV * (HD / 2);
        rope_kernel<<<(totk + 255) / 256, 256>>>(Kp, cosT, sinT, NKV);
    }

    // Causal attention
    {
        dim3 grid(SEQ / BQ, NH);
        attn_kernel<<<grid, BQ>>>(Qp, Kp, Vp, Op);
    }

    // Output projection
    {
        dim3 grid(DMODEL / 128, SEQ / 128);
        sgemm_kernel<<<grid, 256>>>(Op, Wo, out, SEQ, DMODEL, DMODEL);
    }
}

// round 3
// speedup vs baseline: 1.6481x; 1.6481x over previous
#include <cuda_runtime.h>
#include <cuda_fp16.h>
#include <math.h>
#include <stdint.h>

// Problem constants
#define SEQ    2048
#define DMODEL 1024
#define NH     16
#define NKV    4
#define HD     64
#define QKVN   1536         // fused Q(1024) + K(256) + V(256)

// ---------------------------------------------------------------------------
// Scratch (device globals)
// ---------------------------------------------------------------------------
__device__ __half g_x16[SEQ * DMODEL];          // x in fp16 [M][K]
__device__ __half g_Wqkv16[QKVN * DMODEL];      // fused W^T fp16 [N][K]
__device__ __half g_Wo16[DMODEL * DMODEL];      // Wo^T fp16 [N][K]
__device__ float  g_QKV[SEQ * QKVN];            // fused QKV fp32
__device__ __half g_O16[SEQ * DMODEL];          // attention out fp16

__device__ __forceinline__ uint32_t smem_u32(const void* p) {
    return (uint32_t)__cvta_generic_to_shared(p);
}

// ---------------------------------------------------------------------------
// Converts
// ---------------------------------------------------------------------------
__global__ void conv_f16_kernel(const float* __restrict__ in,
                                __half* __restrict__ out, int n) {
    int i = blockIdx.x * blockDim.x + threadIdx.x;
    if (i < n) out[i] = __float2half(in[i]);
}

// W[K][N] fp32 -> out[N][K] fp16 (out may be a slice base)
__global__ __launch_bounds__(256)
void transpose_f16_kernel(const float* __restrict__ W,
                          __half* __restrict__ out, int K, int N) {
    __shared__ float t[32][33];
    int n0 = blockIdx.x * 32, k0 = blockIdx.y * 32;
    int tx = threadIdx.x, ty = threadIdx.y;
    #pragma unroll
    for (int i = ty; i < 32; i += 8)
        t[i][tx] = W[(size_t)(k0 + i) * N + n0 + tx];
    __syncthreads();
    #pragma unroll
    for (int i = ty; i < 32; i += 8)
        out[(size_t)(n0 + i) * K + k0 + tx] = __float2half(t[tx][i]);
}

// ---------------------------------------------------------------------------
// HMMA GEMM: C[M,N] = A[M,K](f16) @ Bt[N,K](f16)^T, f32 accum.
// CTA 128x128, 8 warps (2x4), warp tile 64x32, BK=32.
// ---------------------------------------------------------------------------
#define BM 128
#define BN 128
#define BK 32
#define APAD 8
#define ASTR (BK + APAD)   // 40 halves per row

__device__ __forceinline__ void ldsm_x4(uint32_t* r, uint32_t addr) {
    asm volatile("ldmatrix.sync.aligned.m8n8.x4.shared.b16 {%0,%1,%2,%3}, [%4];"
                 : "=r"(r[0]), "=r"(r[1]), "=r"(r[2]), "=r"(r[3]) : "r"(addr));
}

__device__ __forceinline__ void mma16816(float* c, const uint32_t* a,
                                         uint32_t b0, uint32_t b1) {
    asm volatile(
        "mma.sync.aligned.m16n8k16.row.col.f32.f16.f16.f32 "
        "{%0,%1,%2,%3}, {%4,%5,%6,%7}, {%8,%9}, {%0,%1,%2,%3};"
        : "+f"(c[0]), "+f"(c[1]), "+f"(c[2]), "+f"(c[3])
        : "r"(a[0]), "r"(a[1]), "r"(a[2]), "r"(a[3]), "r"(b0), "r"(b1));
}

__global__ __launch_bounds__(256)
void gemm_hmma_kernel(const __half* __restrict__ A,
                      const __half* __restrict__ Bt,
                      float* __restrict__ C, int M, int N, int K) {
    __shared__ __half As[BM * ASTR];
    __shared__ __half Bs[BN * ASTR];

    const int tid = threadIdx.x;
    const int lane = tid & 31;
    const int wid = tid >> 5;
    const int wm0 = (wid >> 2) * 64;   // warp M offset in tile
    const int wn0 = (wid & 3) * 32;    // warp N offset in tile
    const int row0 = blockIdx.y * BM;
    const int col0 = blockIdx.x * BN;

    // Global load mapping: idx -> (row, c4); 2 per thread per operand
    const int r_a0 = (tid) >> 2,        c_a0 = (tid & 3);
    const int r_a1 = (tid + 256) >> 2,  c_a1 = (tid & 3);

    float acc[4][4][4];
    #pragma unroll
    for (int i = 0; i < 4; i++)
        #pragma unroll
        for (int j = 0; j < 4; j++)
            #pragma unroll
            for (int k = 0; k < 4; k++) acc[i][j][k] = 0.f;

    const uint32_t as_base = smem_u32(As);
    const uint32_t bs_base = smem_u32(Bs);

    // ldmatrix lane addressing (halves)
    const int a_lrow = lane & 15, a_lcol = (lane >> 4) << 3;
    const int b_noff = (lane & 7) + ((lane >> 4) << 3);
    const int b_koff = ((lane >> 3) & 1) << 3;

    uint4 pa0, pa1, pb0, pb1;
    // prefetch chunk 0
    {
        pa0 = *(const uint4*)(A  + (size_t)(row0 + r_a0) * K + c_a0 * 8);
        pa1 = *(const uint4*)(A  + (size_t)(row0 + r_a1) * K + c_a1 * 8);
        pb0 = *(const uint4*)(Bt + (size_t)(col0 + r_a0) * K + c_a0 * 8);
        pb1 = *(const uint4*)(Bt + (size_t)(col0 + r_a1) * K + c_a1 * 8);
    }

    const int nchunks = K / BK;
    for (int c = 0; c < nchunks; c++) {
        // store prefetched chunk to smem
        *(uint4*)(As + r_a0 * ASTR + c_a0 * 8) = pa0;
        *(uint4*)(As + r_a1 * ASTR + c_a1 * 8) = pa1;
        *(uint4*)(Bs + r_a0 * ASTR + c_a0 * 8) = pb0;
        *(uint4*)(Bs + r_a1 * ASTR + c_a1 * 8) = pb1;
        __syncthreads();

        if (c + 1 < nchunks) {
            int k0 = (c + 1) * BK;
            pa0 = *(const uint4*)(A  + (size_t)(row0 + r_a0) * K + k0 + c_a0 * 8);
            pa1 = *(const uint4*)(A  + (size_t)(row0 + r_a1) * K + k0 + c_a1 * 8);
            pb0 = *(const uint4*)(Bt + (size_t)(col0 + r_a0) * K + k0 + c_a0 * 8);
            pb1 = *(const uint4*)(Bt + (size_t)(col0 + r_a1) * K + k0 + c_a1 * 8);
        }

        #pragma unroll
        for (int ks = 0; ks < 2; ks++) {
            uint32_t af[4][4], bf[2][4];
            #pragma unroll
            for (int fm = 0; fm < 4; fm++) {
                uint32_t addr = as_base +
                    2u * ((wm0 + fm * 16 + a_lrow) * ASTR + ks * 16 + a_lcol);
                ldsm_x4(af[fm], addr);
            }
            #pragma unroll
            for (int p = 0; p < 2; p++) {
                uint32_t addr = bs_base +
                    2u * ((wn0 + p * 16 + b_noff) * ASTR + ks * 16 + b_koff);
                ldsm_x4(bf[p], addr);
            }
            #pragma unroll
            for (int fm = 0; fm < 4; fm++)
                #pragma unroll
                for (int fn = 0; fn < 4; fn++)
                    mma16816(acc[fm][fn], af[fm],
                             bf[fn >> 1][(fn & 1) * 2],
                             bf[fn >> 1][(fn & 1) * 2 + 1]);
        }
        __syncthreads();
    }

    // Epilogue
    const int g = lane >> 2, t = lane & 3;
    #pragma unroll
    for (int fm = 0; fm < 4; fm++) {
        #pragma unroll
        for (int fn = 0; fn < 4; fn++) {
            int r = row0 + wm0 + fm * 16 + g;
            int cc = col0 + wn0 + fn * 8 + 2 * t;
            *(float2*)(C + (size_t)r * N + cc) =
                make_float2(acc[fm][fn][0], acc[fm][fn][1]);
            *(float2*)(C + (size_t)(r + 8) * N + cc) =
                make_float2(acc[fm][fn][2], acc[fm][fn][3]);
        }
    }
}

// ---------------------------------------------------------------------------
// RoPE (in place) on a column-slice of fused QKV.
// ---------------------------------------------------------------------------
__global__ void rope_kernel(float* __restrict__ T,
                            const float* __restrict__ cosT,
                            const float* __restrict__ sinT,
                            int nheads) {
    int idx = blockIdx.x * blockDim.x + threadIdx.x;
    int total = SEQ * nheads * (HD / 2);
    if (idx >= total) return;
    int i = idx % (HD / 2);
    int h = (idx / (HD / 2)) % nheads;
    int s = idx / ((HD / 2) * nheads);
    float c  = cosT[s * (HD / 2) + i];
    float sn = sinT[s * (HD / 2) + i];
    float* row = T + (size_t)s * QKVN + h * HD;
    float t1 = row[i];
    float t2 = row[i + HD / 2];
    row[i]          = t1 * c - t2 * sn;
    row[i + HD / 2] = t2 * c + t1 * sn;
}

// ---------------------------------------------------------------------------
// Flash-style causal attention (fp32 SIMT), fused-QKV input, fp16 output.
// ---------------------------------------------------------------------------
#define BQ  64
#define BKT 32

__global__ __launch_bounds__(BQ)
void attn_kernel(const float* __restrict__ QKV, __half* __restrict__ O) {
    const int qt  = blockIdx.x;
    const int h   = blockIdx.y;
    const int kvh = h / (NH / NKV);
    const int row = threadIdx.x;
    const int qg  = qt * BQ + row;

    __shared__ float Qs[BQ][HD + 1];
    __shared__ float Ks[BKT][HD];
    __shared__ float Vs[BKT][HD];

    for (int i = threadIdx.x; i < BQ * HD; i += BQ) {
        int r = i / HD, d = i % HD;
        Qs[r][d] = QKV[(size_t)(qt * BQ + r) * QKVN + h * HD + d];
    }

    float acc[HD];
    #pragma unroll
    for (int d = 0; d < HD; d++) acc[d] = 0.f;
    float m = -INFINITY;
    float l = 0.f;
    const float scale = 0.125f;

    const int nkt = ((qt + 1) * BQ) / BKT;

    for (int t = 0; t < nkt; t++) {
        __syncthreads();
        for (int i = threadIdx.x; i < BKT * HD; i += BQ) {
            int r = i / HD, d = i % HD;
            size_t base = (size_t)(t * BKT + r) * QKVN + kvh * HD + d;
            Ks[r][d] = QKV[base + 1024];   // K slice
            Vs[r][d] = QKV[base + 1280];   // V slice
        }
        __syncthreads();

        float sc[BKT];
        #pragma unroll
        for (int j = 0; j < BKT; j++) sc[j] = 0.f;
        #pragma unroll 4
        for (int d = 0; d < HD; d++) {
            float qv = Qs[row][d];
            #pragma unroll
            for (int j = 0; j < BKT; j++)
                sc[j] = fmaf(qv, Ks[j][d], sc[j]);
        }

        float mt = m;
        #pragma unroll
        for (int j = 0; j < BKT; j++) {
            int kg = t * BKT + j;
            sc[j] = (kg <= qg) ? sc[j] * scale : -INFINITY;
            mt = fmaxf(mt, sc[j]);
        }

        float corr = __expf(m - mt);
        float psum = 0.f;
        #pragma unroll
        for (int j = 0; j < BKT; j++) {
            sc[j] = __expf(sc[j] - mt);
            psum += sc[j];
        }
        l = l * corr + psum;
        m = mt;

        #pragma unroll
        for (int d = 0; d < HD; d++) acc[d] *= corr;
        for (int j = 0; j < BKT; j++) {
            float pj = sc[j];
            #pragma unroll
            for (int d = 0; d < HD; d++)
                acc[d] = fmaf(pj, Vs[j][d], acc[d]);
        }
    }

    float inv_l = 1.f / l;
    #pragma unroll
    for (int d = 0; d < HD; d++)
        O[(size_t)qg * DMODEL + h * HD + d] = __float2half(acc[d] * inv_l);
}

// ---------------------------------------------------------------------------
// Launch. Inputs: x, rope_cos, rope_sin, Wq, Wk, Wv, Wo
// ---------------------------------------------------------------------------
extern "C" void kernel_launch(void* const* d_in, const int* in_sizes, int n_in,
                              void* d_out, int out_size) {
    const float* x    = (const float*)d_in[0];
    const float* cosT = (const float*)d_in[1];
    const float* sinT = (const float*)d_in[2];
    const float* Wq   = (const float*)d_in[3];
    const float* Wk   = (const float*)d_in[4];
    const float* Wv   = (const float*)d_in[5];
    const float* Wo   = (const float*)d_in[6];
    float* out = (float*)d_out;

    __half *x16, *wqkv16, *wo16, *o16;
    float *qkv;
    cudaGetSymbolAddress((void**)&x16,    g_x16);
    cudaGetSymbolAddress((void**)&wqkv16, g_Wqkv16);
    cudaGetSymbolAddress((void**)&wo16,   g_Wo16);
    cudaGetSymbolAddress((void**)&qkv,    g_QKV);
    cudaGetSymbolAddress((void**)&o16,    g_O16);

    // Converts
    {
        int n = SEQ * DMODEL;
        conv_f16_kernel<<<(n + 255) / 256, 256>>>(x, x16, n);
    }
    {
        dim3 blk(32, 8);
        // Wq -> rows 0..1023 of fused W^T
        transpose_f16_kernel<<<dim3(DMODEL / 32, DMODEL / 32), blk>>>(
            Wq, wqkv16, DMODEL, DMODEL);
        // Wk -> rows 1024..1279
        transpose_f16_kernel<<<dim3((NKV * HD) / 32, DMODEL / 32), blk>>>(
            Wk, wqkv16 + (size_t)1024 * DMODEL, DMODEL, NKV * HD);
        // Wv -> rows 1280..1535
        transpose_f16_kernel<<<dim3((NKV * HD) / 32, DMODEL / 32), blk>>>(
            Wv, wqkv16 + (size_t)1280 * DMODEL, DMODEL, NKV * HD);
        // Wo
        transpose_f16_kernel<<<dim3(DMODEL / 32, DMODEL / 32), blk>>>(
            Wo, wo16, DMODEL, DMODEL);
    }

    // Fused QKV projection
    gemm_hmma_kernel<<<dim3(QKVN / BN, SEQ / BM), 256>>>(
        x16, wqkv16, qkv, SEQ, QKVN, DMODEL);

    // RoPE on Q (cols 0..1023) and K (cols 1024..1279)
    {
        int totq = SEQ * NH * (HD / 2);
        rope_kernel<<<(totq + 255) / 256, 256>>>(qkv, cosT, sinT, NH);
        int totk = SEQ * NKV * (HD / 2);
        rope_kernel<<<(totk + 255) / 256, 256>>>(qkv + 1024, cosT, sinT, NKV);
    }

    // Attention
    {
        dim3 grid(SEQ / BQ, NH);
        attn_kernel<<<grid, BQ>>>(qkv, o16);
    }

    // Output projection
    gemm_hmma_kernel<<<dim3(DMODEL / BN, SEQ / BM), 256>>>(
        o16, wo16, out, SEQ, DMODEL, DMODEL);
}

// round 4
// speedup vs baseline: 6.3421x; 3.8481x over previous
#include <cuda_runtime.h>
#include <cuda_fp16.h>
#include <math.h>
#include <stdint.h>

// Problem constants
#define SEQ    2048
#define DMODEL 1024
#define NH     16
#define NKV    4
#define HD     64
#define QKVN   1536         // fused Q(1024) + K(256) + V(256)
#define KVW    256          // NKV*HD

// ---------------------------------------------------------------------------
// Scratch (device globals)
// ---------------------------------------------------------------------------
__device__ __half g_x16[SEQ * DMODEL];
__device__ __half g_Wqkv16[QKVN * DMODEL];
__device__ __half g_Wo16[DMODEL * DMODEL];
__device__ float  g_QKV[SEQ * QKVN];
__device__ __half g_O16[SEQ * DMODEL];
// hi/lo fp16 for attention operands
__device__ __half g_Qh[SEQ * DMODEL], g_Ql[SEQ * DMODEL];
__device__ __half g_Kh[SEQ * KVW],   g_Kl[SEQ * KVW];
__device__ __half g_Vh[SEQ * KVW],   g_Vl[SEQ * KVW];

__device__ __forceinline__ uint32_t smem_u32(const void* p) {
    return (uint32_t)__cvta_generic_to_shared(p);
}

// ---------------------------------------------------------------------------
// Converts
// ---------------------------------------------------------------------------
__global__ void conv_f16_kernel(const float* __restrict__ in,
                                __half* __restrict__ out, int n) {
    int i = blockIdx.x * blockDim.x + threadIdx.x;
    if (i < n) out[i] = __float2half(in[i]);
}

// W[K][N] fp32 -> out[N][K] fp16
__global__ __launch_bounds__(256)
void transpose_f16_kernel(const float* __restrict__ W,
                          __half* __restrict__ out, int K, int N) {
    __shared__ float t[32][33];
    int n0 = blockIdx.x * 32, k0 = blockIdx.y * 32;
    int tx = threadIdx.x, ty = threadIdx.y;
    #pragma unroll
    for (int i = ty; i < 32; i += 8)
        t[i][tx] = W[(size_t)(k0 + i) * N + n0 + tx];
    __syncthreads();
    #pragma unroll
    for (int i = ty; i < 32; i += 8)
        out[(size_t)(n0 + i) * K + k0 + tx] = __float2half(t[tx][i]);
}

// ---------------------------------------------------------------------------
// HMMA GEMM (unchanged from round 3)
// ---------------------------------------------------------------------------
#define BM 128
#define BN 128
#define BK 32
#define APAD 8
#define ASTR (BK + APAD)

__device__ __forceinline__ void ldsm_x4(uint32_t* r, uint32_t addr) {
    asm volatile("ldmatrix.sync.aligned.m8n8.x4.shared.b16 {%0,%1,%2,%3}, [%4];"
                 : "=r"(r[0]), "=r"(r[1]), "=r"(r[2]), "=r"(r[3]) : "r"(addr));
}
__device__ __forceinline__ void ldsm_x4_trans(uint32_t* r, uint32_t addr) {
    asm volatile("ldmatrix.sync.aligned.m8n8.x4.trans.shared.b16 {%0,%1,%2,%3}, [%4];"
                 : "=r"(r[0]), "=r"(r[1]), "=r"(r[2]), "=r"(r[3]) : "r"(addr));
}

__device__ __forceinline__ void mma16816(float* c, const uint32_t* a,
                                         uint32_t b0, uint32_t b1) {
    asm volatile(
        "mma.sync.aligned.m16n8k16.row.col.f32.f16.f16.f32 "
        "{%0,%1,%2,%3}, {%4,%5,%6,%7}, {%8,%9}, {%0,%1,%2,%3};"
        : "+f"(c[0]), "+f"(c[1]), "+f"(c[2]), "+f"(c[3])
        : "r"(a[0]), "r"(a[1]), "r"(a[2]), "r"(a[3]), "r"(b0), "r"(b1));
}

__global__ __launch_bounds__(256)
void gemm_hmma_kernel(const __half* __restrict__ A,
                      const __half* __restrict__ Bt,
                      float* __restrict__ C, int M, int N, int K) {
    __shared__ __half As[BM * ASTR];
    __shared__ __half Bs[BN * ASTR];

    const int tid = threadIdx.x;
    const int lane = tid & 31;
    const int wid = tid >> 5;
    const int wm0 = (wid >> 2) * 64;
    const int wn0 = (wid & 3) * 32;
    const int row0 = blockIdx.y * BM;
    const int col0 = blockIdx.x * BN;

    const int r_a0 = (tid) >> 2,        c_a0 = (tid & 3);
    const int r_a1 = (tid + 256) >> 2,  c_a1 = (tid & 3);

    float acc[4][4][4];
    #pragma unroll
    for (int i = 0; i < 4; i++)
        #pragma unroll
        for (int j = 0; j < 4; j++)
            #pragma unroll
            for (int k = 0; k < 4; k++) acc[i][j][k] = 0.f;

    const uint32_t as_base = smem_u32(As);
    const uint32_t bs_base = smem_u32(Bs);

    const int a_lrow = lane & 15, a_lcol = (lane >> 4) << 3;
    const int b_noff = (lane & 7) + ((lane >> 4) << 3);
    const int b_koff = ((lane >> 3) & 1) << 3;

    uint4 pa0, pa1, pb0, pb1;
    {
        pa0 = *(const uint4*)(A  + (size_t)(row0 + r_a0) * K + c_a0 * 8);
        pa1 = *(const uint4*)(A  + (size_t)(row0 + r_a1) * K + c_a1 * 8);
        pb0 = *(const uint4*)(Bt + (size_t)(col0 + r_a0) * K + c_a0 * 8);
        pb1 = *(const uint4*)(Bt + (size_t)(col0 + r_a1) * K + c_a1 * 8);
    }

    const int nchunks = K / BK;
    for (int c = 0; c < nchunks; c++) {
        *(uint4*)(As + r_a0 * ASTR + c_a0 * 8) = pa0;
        *(uint4*)(As + r_a1 * ASTR + c_a1 * 8) = pa1;
        *(uint4*)(Bs + r_a0 * ASTR + c_a0 * 8) = pb0;
        *(uint4*)(Bs + r_a1 * ASTR + c_a1 * 8) = pb1;
        __syncthreads();

        if (c + 1 < nchunks) {
            int k0 = (c + 1) * BK;
            pa0 = *(const uint4*)(A  + (size_t)(row0 + r_a0) * K + k0 + c_a0 * 8);
            pa1 = *(const uint4*)(A  + (size_t)(row0 + r_a1) * K + k0 + c_a1 * 8);
            pb0 = *(const uint4*)(Bt + (size_t)(col0 + r_a0) * K + k0 + c_a0 * 8);
            pb1 = *(const uint4*)(Bt + (size_t)(col0 + r_a1) * K + k0 + c_a1 * 8);
        }

        #pragma unroll
        for (int ks = 0; ks < 2; ks++) {
            uint32_t af[4][4], bf[2][4];
            #pragma unroll
            for (int fm = 0; fm < 4; fm++) {
                uint32_t addr = as_base +
                    2u * ((wm0 + fm * 16 + a_lrow) * ASTR + ks * 16 + a_lcol);
                ldsm_x4(af[fm], addr);
            }
            #pragma unroll
            for (int p = 0; p < 2; p++) {
                uint32_t addr = bs_base +
                    2u * ((wn0 + p * 16 + b_noff) * ASTR + ks * 16 + b_koff);
                ldsm_x4(bf[p], addr);
            }
            #pragma unroll
            for (int fm = 0; fm < 4; fm++)
                #pragma unroll
                for (int fn = 0; fn < 4; fn++)
                    mma16816(acc[fm][fn], af[fm],
                             bf[fn >> 1][(fn & 1) * 2],
                             bf[fn >> 1][(fn & 1) * 2 + 1]);
        }
        __syncthreads();
    }

    const int g = lane >> 2, t = lane & 3;
    #pragma unroll
    for (int fm = 0; fm < 4; fm++) {
        #pragma unroll
        for (int fn = 0; fn < 4; fn++) {
            int r = row0 + wm0 + fm * 16 + g;
            int cc = col0 + wn0 + fn * 8 + 2 * t;
            *(float2*)(C + (size_t)r * N + cc) =
                make_float2(acc[fm][fn][0], acc[fm][fn][1]);
            *(float2*)(C + (size_t)(r + 8) * N + cc) =
                make_float2(acc[fm][fn][2], acc[fm][fn][3]);
        }
    }
}

// ---------------------------------------------------------------------------
// RoPE + hi/lo split: fp32 fused-QKV slice -> fp16 hi/lo buffers.
// ---------------------------------------------------------------------------
__global__ void rope_split_kernel(const float* __restrict__ QKV,
                                  const float* __restrict__ cosT,
                                  const float* __restrict__ sinT,
                                  int nheads, int col0,
                                  __half* __restrict__ outH,
                                  __half* __restrict__ outL, int outw) {
    int idx = blockIdx.x * blockDim.x + threadIdx.x;
    int total = SEQ * nheads * 32;
    if (idx >= total) return;
    int i = idx % 32;
    int h = (idx / 32) % nheads;
    int s = idx / (32 * nheads);
    float c  = cosT[s * 32 + i];
    float sn = sinT[s * 32 + i];
    const float* row = QKV + (size_t)s * QKVN + col0 + h * HD;
    float t1 = row[i], t2 = row[i + 32];
    float r1 = t1 * c - t2 * sn;
    float r2 = t2 * c + t1 * sn;
    size_t o = (size_t)s * outw + h * HD + i;
    __half h1 = __float2half(r1);
    __half h2 = __float2half(r2);
    outH[o]      = h1;  outL[o]      = __float2half(r1 - __half2float(h1));
    outH[o + 32] = h2;  outL[o + 32] = __float2half(r2 - __half2float(h2));
}

__global__ void v_split_kernel(const float* __restrict__ QKV,
                               __half* __restrict__ Vh,
                               __half* __restrict__ Vl) {
    int idx = blockIdx.x * blockDim.x + threadIdx.x;
    if (idx >= SEQ * KVW) return;
    int s = idx / KVW, j = idx % KVW;
    float v = QKV[(size_t)s * QKVN + 1280 + j];
    __half h = __float2half(v);
    Vh[idx] = h;
    Vl[idx] = __float2half(v - __half2float(h));
}

// ---------------------------------------------------------------------------
// Tensor-core flash attention. 4 warps, BQ=64 (16 rows/warp), BK=64.
// 3-term hi/lo fp16 emulation on both mmas for fp32-grade accuracy.
// ---------------------------------------------------------------------------
#define ATS 72                 // smem row stride (halves): ldsm conflict-free
#define ATILE (64 * ATS)       // halves per tile buffer

__device__ __forceinline__ uint32_t pack_h2(float a, float b) {
    __half2 h = __floats2half2_rn(a, b);
    return *(uint32_t*)&h;
}

__global__ __launch_bounds__(128)
void attn_mma_kernel(const __half* __restrict__ Qh_, const __half* __restrict__ Ql_,
                     const __half* __restrict__ Kh_, const __half* __restrict__ Kl_,
                     const __half* __restrict__ Vh_, const __half* __restrict__ Vl_,
                     __half* __restrict__ O) {
    extern __shared__ __half sm[];
    __half* QsH = sm;
    __half* QsL = sm + ATILE;
    __half* KsH = sm + 2 * ATILE;
    __half* KsL = sm + 3 * ATILE;
    __half* VsH = sm + 4 * ATILE;
    __half* VsL = sm + 5 * ATILE;

    const int qt  = blockIdx.x;          // q tile (64 rows)
    const int h   = blockIdx.y;          // head
    const int kvh = h / (NH / NKV);
    const int tid = threadIdx.x;
    const int lane = tid & 31;
    const int wid = tid >> 5;            // warp q-offset = wid*16

    const int lr = tid >> 1;             // 0..63 (load row)
    const int lc = (tid & 1) * 32;       // 0 / 32

    // Load Q tile (hi/lo)
    {
        const __half* sh = Qh_ + (size_t)(qt * 64 + lr) * DMODEL + h * HD + lc;
        const __half* sl = Ql_ + (size_t)(qt * 64 + lr) * DMODEL + h * HD + lc;
        #pragma unroll
        for (int j = 0; j < 4; j++) {
            *(uint4*)(QsH + lr * ATS + lc + 8 * j) = *(const uint4*)(sh + 8 * j);
            *(uint4*)(QsL + lr * ATS + lc + 8 * j) = *(const uint4*)(sl + 8 * j);
        }
    }
    __syncthreads();

    const uint32_t qsh = smem_u32(QsH), qsl = smem_u32(QsL);
    const uint32_t ksh = smem_u32(KsH), ksl = smem_u32(KsL);
    const uint32_t vsh = smem_u32(VsH), vsl = smem_u32(VsL);

    const int a_lrow = lane & 15, a_lcol = (lane >> 4) << 3;
    const int b_noff = (lane & 7) + ((lane >> 4) << 3);
    const int b_koff = ((lane >> 3) & 1) << 3;

    // Q fragments (persist)
    uint32_t qfh[4][4], qfl[4][4];
    #pragma unroll
    for (int kk = 0; kk < 4; kk++) {
        uint32_t ao = 2u * ((wid * 16 + a_lrow) * ATS + kk * 16 + a_lcol);
        ldsm_x4(qfh[kk], qsh + ao);
        ldsm_x4(qfl[kk], qsl + ao);
    }

    const int g = lane >> 2, t = lane & 3;
    const int qg0 = qt * 64 + wid * 16 + g;
    const int qg1 = qg0 + 8;

    float o[8][4];
    #pragma unroll
    for (int nj = 0; nj < 8; nj++)
        #pragma unroll
        for (int e = 0; e < 4; e++) o[nj][e] = 0.f;
    float m0 = -INFINITY, m1 = -INFINITY, l0 = 0.f, l1 = 0.f;
    const float scale = 0.125f;

    for (int kt = 0; kt <= qt; kt++) {
        __syncthreads();
        // Load K/V tiles (hi/lo)
        {
            size_t gbase = (size_t)(kt * 64 + lr) * KVW + kvh * HD + lc;
            #pragma unroll
            for (int j = 0; j < 4; j++) {
                *(uint4*)(KsH + lr * ATS + lc + 8 * j) = *(const uint4*)(Kh_ + gbase + 8 * j);
                *(uint4*)(KsL + lr * ATS + lc + 8 * j) = *(const uint4*)(Kl_ + gbase + 8 * j);
                *(uint4*)(VsH + lr * ATS + lc + 8 * j) = *(const uint4*)(Vh_ + gbase + 8 * j);
                *(uint4*)(VsL + lr * ATS + lc + 8 * j) = *(const uint4*)(Vl_ + gbase + 8 * j);
            }
        }
        __syncthreads();

        // S = Q K^T  (3-term hi/lo)
        float s[8][4];
        #pragma unroll
        for (int nj = 0; nj < 8; nj++)
            #pragma unroll
            for (int e = 0; e < 4; e++) s[nj][e] = 0.f;

        #pragma unroll
        for (int nj16 = 0; nj16 < 4; nj16++) {
            #pragma unroll
            for (int kk = 0; kk < 4; kk++) {
                uint32_t bo = 2u * ((nj16 * 16 + b_noff) * ATS + kk * 16 + b_koff);
                uint32_t bh[4], bl[4];
                ldsm_x4(bh, ksh + bo);
                ldsm_x4(bl, ksl + bo);
                mma16816(s[2 * nj16],     qfh[kk], bh[0], bh[1]);
                mma16816(s[2 * nj16],     qfl[kk], bh[0], bh[1]);
                mma16816(s[2 * nj16],     qfh[kk], bl[0], bl[1]);
                mma16816(s[2 * nj16 + 1], qfh[kk], bh[2], bh[3]);
                mma16816(s[2 * nj16 + 1], qfl[kk], bh[2], bh[3]);
                mma16816(s[2 * nj16 + 1], qfh[kk], bl[2], bl[3]);
            }
        }

        // Scale + causal mask + row max
        float mt0 = m0, mt1 = m1;
        const bool need_mask = (kt == qt);
        #pragma unroll
        for (int nj = 0; nj < 8; nj++) {
            int kg = kt * 64 + nj * 8 + 2 * t;
            #pragma unroll
            for (int e = 0; e < 4; e++) s[nj][e] *= scale;
            if (need_mask) {
                if (kg     > qg0) s[nj][0] = -INFINITY;
                if (kg + 1 > qg0) s[nj][1] = -INFINITY;
                if (kg     > qg1) s[nj][2] = -INFINITY;
                if (kg + 1 > qg1) s[nj][3] = -INFINITY;
            }
            mt0 = fmaxf(mt0, fmaxf(s[nj][0], s[nj][1]));
            mt1 = fmaxf(mt1, fmaxf(s[nj][2], s[nj][3]));
        }
        mt0 = fmaxf(mt0, __shfl_xor_sync(0xffffffffu, mt0, 1));
        mt0 = fmaxf(mt0, __shfl_xor_sync(0xffffffffu, mt0, 2));
        mt1 = fmaxf(mt1, __shfl_xor_sync(0xffffffffu, mt1, 1));
        mt1 = fmaxf(mt1, __shfl_xor_sync(0xffffffffu, mt1, 2));

        float corr0 = __expf(m0 - mt0);
        float corr1 = __expf(m1 - mt1);
        float ps0 = 0.f, ps1 = 0.f;
        #pragma unroll
        for (int nj = 0; nj < 8; nj++) {
            s[nj][0] = __expf(s[nj][0] - mt0);
            s[nj][1] = __expf(s[nj][1] - mt0);
            s[nj][2] = __expf(s[nj][2] - mt1);
            s[nj][3] = __expf(s[nj][3] - mt1);
            ps0 += s[nj][0] + s[nj][1];
            ps1 += s[nj][2] + s[nj][3];
        }
        ps0 += __shfl_xor_sync(0xffffffffu, ps0, 1);
        ps0 += __shfl_xor_sync(0xffffffffu, ps0, 2);
        ps1 += __shfl_xor_sync(0xffffffffu, ps1, 1);
        ps1 += __shfl_xor_sync(0xffffffffu, ps1, 2);
        l0 = l0 * corr0 + ps0;  m0 = mt0;
        l1 = l1 * corr1 + ps1;  m1 = mt1;

        #pragma unroll
        for (int nj = 0; nj < 8; nj++) {
            o[nj][0] *= corr0;  o[nj][1] *= corr0;
            o[nj][2] *= corr1;  o[nj][3] *= corr1;
        }

        // O += P V  (3-term hi/lo), V via ldmatrix.trans
        #pragma unroll
        for (int kk = 0; kk < 4; kk++) {
            // Build P a-frags (hi/lo) from s[2kk], s[2kk+1]
            uint32_t pah[4], pal[4];
            {
                float v00 = s[2 * kk][0],     v01 = s[2 * kk][1];
                float v10 = s[2 * kk][2],     v11 = s[2 * kk][3];
                float v20 = s[2 * kk + 1][0], v21 = s[2 * kk + 1][1];
                float v30 = s[2 * kk + 1][2], v31 = s[2 * kk + 1][3];
                pah[0] = pack_h2(v00, v01);
                pah[1] = pack_h2(v10, v11);
                pah[2] = pack_h2(v20, v21);
                pah[3] = pack_h2(v30, v31);
                __half2* hp = (__half2*)pah;
                pal[0] = pack_h2(v00 - __low2float(hp[0]),  v01 - __high2float(hp[0]));
                pal[1] = pack_h2(v10 - __low2float(hp[1]),  v11 - __high2float(hp[1]));
                pal[2] = pack_h2(v20 - __low2float(hp[2]),  v21 - __high2float(hp[2]));
                pal[3] = pack_h2(v30 - __low2float(hp[3]),  v31 - __high2float(hp[3]));
            }
            #pragma unroll
            for (int dj16 = 0; dj16 < 4; dj16++) {
                uint32_t vo = 2u * ((kk * 16 + (lane & 15)) * ATS +
                                    dj16 * 16 + ((lane >> 4) << 3));
                uint32_t bh[4], bl[4];
                ldsm_x4_trans(bh, vsh + vo);
                ldsm_x4_trans(bl, vsl + vo);
                mma16816(o[2 * dj16],     pah, bh[0], bh[1]);
                mma16816(o[2 * dj16],     pal, bh[0], bh[1]);
                mma16816(o[2 * dj16],     pah, bl[0], bl[1]);
                mma16816(o[2 * dj16 + 1], pah, bh[2], bh[3]);
                mma16816(o[2 * dj16 + 1], pal, bh[2], bh[3]);
                mma16816(o[2 * dj16 + 1], pah, bl[2], bl[3]);
            }
        }
    }

    // Write O (fp16)
    float inv0 = 1.f / l0, inv1 = 1.f / l1;
    #pragma unroll
    for (int nj = 0; nj < 8; nj++) {
        int col = h * HD + nj * 8 + 2 * t;
        __half2 v0 = __floats2half2_rn(o[nj][0] * inv0, o[nj][1] * inv0);
        __half2 v1 = __floats2half2_rn(o[nj][2] * inv1, o[nj][3] * inv1);
        *(__half2*)(O + (size_t)qg0 * DMODEL + col) = v0;
        *(__half2*)(O + (size_t)qg1 * DMODEL + col) = v1;
    }
}

// ---------------------------------------------------------------------------
// Launch. Inputs: x, rope_cos, rope_sin, Wq, Wk, Wv, Wo
// ---------------------------------------------------------------------------
extern "C" void kernel_launch(void* const* d_in, const int* in_sizes, int n_in,
                              void* d_out, int out_size) {
    const float* x    = (const float*)d_in[0];
    const float* cosT = (const float*)d_in[1];
    const float* sinT = (const float*)d_in[2];
    const float* Wq   = (const float*)d_in[3];
    const float* Wk   = (const float*)d_in[4];
    const float* Wv   = (const float*)d_in[5];
    const float* Wo   = (const float*)d_in[6];
    float* out = (float*)d_out;

    __half *x16, *wqkv16, *wo16, *o16, *qh, *ql, *kh, *kl, *vh, *vl;
    float *qkv;
    cudaGetSymbolAddress((void**)&x16,    g_x16);
    cudaGetSymbolAddress((void**)&wqkv16, g_Wqkv16);
    cudaGetSymbolAddress((void**)&wo16,   g_Wo16);
    cudaGetSymbolAddress((void**)&qkv,    g_QKV);
    cudaGetSymbolAddress((void**)&o16,    g_O16);
    cudaGetSymbolAddress((void**)&qh, g_Qh);  cudaGetSymbolAddress((void**)&ql, g_Ql);
    cudaGetSymbolAddress((void**)&kh, g_Kh);  cudaGetSymbolAddress((void**)&kl, g_Kl);
    cudaGetSymbolAddress((void**)&vh, g_Vh);  cudaGetSymbolAddress((void**)&vl, g_Vl);

    const int attn_smem = 6 * ATILE * 2;   // 55296 bytes
    cudaFuncSetAttribute(attn_mma_kernel,
                         cudaFuncAttributeMaxDynamicSharedMemorySize, attn_smem);

    // Converts
    {
        int n = SEQ * DMODEL;
        conv_f16_kernel<<<(n + 255) / 256, 256>>>(x, x16, n);
    }
    {
        dim3 blk(32, 8);
        transpose_f16_kernel<<<dim3(DMODEL / 32, DMODEL / 32), blk>>>(
            Wq, wqkv16, DMODEL, DMODEL);
        transpose_f16_kernel<<<dim3(KVW / 32, DMODEL / 32), blk>>>(
            Wk, wqkv16 + (size_t)1024 * DMODEL, DMODEL, KVW);
        transpose_f16_kernel<<<dim3(KVW / 32, DMODEL / 32), blk>>>(
            Wv, wqkv16 + (size_t)1280 * DMODEL, DMODEL, KVW);
        transpose_f16_kernel<<<dim3(DMODEL / 32, DMODEL / 32), blk>>>(
            Wo, wo16, DMODEL, DMODEL);
    }

    // Fused QKV projection
    gemm_hmma_kernel<<<dim3(QKVN / BN, SEQ / BM), 256>>>(
        x16, wqkv16, qkv, SEQ, QKVN, DMODEL);

    // RoPE + hi/lo split for Q, K; split V
    {
        int totq = SEQ * NH * 32;
        rope_split_kernel<<<(totq + 255) / 256, 256>>>(
            qkv, cosT, sinT, NH, 0, qh, ql, DMODEL);
        int totk = SEQ * NKV * 32;
        rope_split_kernel<<<(totk + 255) / 256, 256>>>(
            qkv, cosT, sinT, NKV, 1024, kh, kl, KVW);
        int totv = SEQ * KVW;
        v_split_kernel<<<(totv + 255) / 256, 256>>>(qkv, vh, vl);
    }

    // Tensor-core flash attention
    {
        dim3 grid(SEQ / 64, NH);
        attn_mma_kernel<<<grid, 128, attn_smem>>>(qh, ql, kh, kl, vh, vl, o16);
    }

    // Output projection
    gemm_hmma_kernel<<<dim3(DMODEL / BN, SEQ / BM), 256>>>(
        o16, wo16, out, SEQ, DMODEL, DMODEL);
}

// round 8
// speedup vs baseline: 7.4130x; 1.1689x over previous
#include <cuda_runtime.h>
#include <cuda_fp16.h>
#include <math.h>
#include <stdint.h>

// Problem constants
#define SEQ    2048
#define DMODEL 1024
#define NH     16
#define NKV    4
#define HD     64
#define QKVN   1536         // fused Q(1024) + K(256) + V(256)
#define KVW    256          // NKV*HD

// ---------------------------------------------------------------------------
// Scratch (device globals)
// ---------------------------------------------------------------------------
__device__ __half g_x16[SEQ * DMODEL];
__device__ __half g_Wqkv16[DMODEL * QKVN];     // [K][N] row-major fp16 (fused)
__device__ __half g_Wo16[DMODEL * DMODEL];     // [K][N] row-major fp16
__device__ float  g_QKV[SEQ * QKVN];
__device__ __half g_O16[SEQ * DMODEL];
__device__ __half g_Qh[SEQ * DMODEL], g_Ql[SEQ * DMODEL];
__device__ __half g_Kh[SEQ * KVW],   g_Kl[SEQ * KVW];
__device__ __half g_Vh[SEQ * KVW];

__device__ __forceinline__ uint32_t smem_u32(const void* p) {
    return (uint32_t)__cvta_generic_to_shared(p);
}

// ---------------------------------------------------------------------------
// cp.async helpers
// ---------------------------------------------------------------------------
__device__ __forceinline__ void cp_async16(uint32_t dst, const void* src) {
    asm volatile("cp.async.cg.shared.global [%0], [%1], 16;"
                 :: "r"(dst), "l"(src));
}
__device__ __forceinline__ void cp_commit() {
    asm volatile("cp.async.commit_group;");
}
template <int N>
__device__ __forceinline__ void cp_wait() {
    asm volatile("cp.async.wait_group %0;" :: "n"(N));
}

// ---------------------------------------------------------------------------
// Converts
// ---------------------------------------------------------------------------
__global__ void conv_f16_kernel(const float* __restrict__ in,
                                __half* __restrict__ out, int n) {
    int i = blockIdx.x * blockDim.x + threadIdx.x;
    if (i < n) out[i] = __float2half(in[i]);
}

// Fuse Wq|Wk|Wv (each [D][*]) into [D][1536] fp16
__global__ void conv_wqkv_kernel(const float* __restrict__ Wq,
                                 const float* __restrict__ Wk,
                                 const float* __restrict__ Wv,
                                 __half* __restrict__ out) {
    int i = blockIdx.x * blockDim.x + threadIdx.x;
    if (i >= DMODEL * QKVN) return;
    int k = i / QKVN, n = i % QKVN;
    float v;
    if (n < 1024)       v = Wq[k * 1024 + n];
    else if (n < 1280)  v = Wk[k * 256 + (n - 1024)];
    else                v = Wv[k * 256 + (n - 1280)];
    out[i] = __float2half(v);
}

// ---------------------------------------------------------------------------
// HMMA GEMM, 2-stage cp.async pipeline.
// C[M,N] = A[M,K](f16) @ B[K,N](f16), f32 accum. B row-major via ldsm.trans.
// CTA 128x128, 8 warps (2x4), warp tile 64x32, BK=32.
// ---------------------------------------------------------------------------
#define BM 128
#define BN 128
#define BK 32
#define ASTR 40      // halves
#define BSTR 136     // halves

__device__ __forceinline__ void ldsm_x4(uint32_t* r, uint32_t addr) {
    asm volatile("ldmatrix.sync.aligned.m8n8.x4.shared.b16 {%0,%1,%2,%3}, [%4];"
                 : "=r"(r[0]), "=r"(r[1]), "=r"(r[2]), "=r"(r[3]) : "r"(addr));
}
__device__ __forceinline__ void ldsm_x4_trans(uint32_t* r, uint32_t addr) {
    asm volatile("ldmatrix.sync.aligned.m8n8.x4.trans.shared.b16 {%0,%1,%2,%3}, [%4];"
                 : "=r"(r[0]), "=r"(r[1]), "=r"(r[2]), "=r"(r[3]) : "r"(addr));
}
__device__ __forceinline__ void mma16816(float* c, const uint32_t* a,
                                         uint32_t b0, uint32_t b1) {
    asm volatile(
        "mma.sync.aligned.m16n8k16.row.col.f32.f16.f16.f32 "
        "{%0,%1,%2,%3}, {%4,%5,%6,%7}, {%8,%9}, {%0,%1,%2,%3};"
        : "+f"(c[0]), "+f"(c[1]), "+f"(c[2]), "+f"(c[3])
        : "r"(a[0]), "r"(a[1]), "r"(a[2]), "r"(a[3]), "r"(b0), "r"(b1));
}

__global__ __launch_bounds__(256)
void gemm_hmma_kernel(const __half* __restrict__ A,
                      const __half* __restrict__ B,
                      float* __restrict__ C, int M, int N, int K) {
    __shared__ __half As[2][BM * ASTR];
    __shared__ __half Bs[2][BK * BSTR];

    const int tid = threadIdx.x;
    const int lane = tid & 31;
    const int wid = tid >> 5;
    const int wm0 = (wid >> 2) * 64;
    const int wn0 = (wid & 3) * 32;
    const int row0 = blockIdx.y * BM;
    const int col0 = blockIdx.x * BN;

    // load mappings
    const int ra = tid >> 2, ca = tid & 3;      // A: rows ra, ra+64; 8 halves
    const int rb = tid >> 4, cb = tid & 15;     // B: rows rb, rb+16; 8 halves

    float acc[4][4][4];
    #pragma unroll
    for (int i = 0; i < 4; i++)
        #pragma unroll
        for (int j = 0; j < 4; j++)
            #pragma unroll
            for (int k = 0; k < 4; k++) acc[i][j][k] = 0.f;

    const uint32_t as0 = smem_u32(As[0]), as1 = smem_u32(As[1]);
    const uint32_t bs0 = smem_u32(Bs[0]), bs1 = smem_u32(Bs[1]);

    const int a_lrow = lane & 15, a_lcol = (lane >> 4) << 3;
    const int b_krow = lane & 15, b_ncol = (lane >> 4) << 3;

    const int nchunks = K / BK;

    // issue loads for a chunk into a stage
    auto load_stage = [&](uint32_t asb, uint32_t bsb, int c) {
        int k0 = c * BK;
        cp_async16(asb + 2u * (ra * ASTR + ca * 8),
                   A + (size_t)(row0 + ra) * K + k0 + ca * 8);
        cp_async16(asb + 2u * ((ra + 64) * ASTR + ca * 8),
                   A + (size_t)(row0 + ra + 64) * K + k0 + ca * 8);
        cp_async16(bsb + 2u * (rb * BSTR + cb * 8),
                   B + (size_t)(k0 + rb) * N + col0 + cb * 8);
        cp_async16(bsb + 2u * ((rb + 16) * BSTR + cb * 8),
                   B + (size_t)(k0 + rb + 16) * N + col0 + cb * 8);
    };

    load_stage(as0, bs0, 0);
    cp_commit();

    for (int c = 0; c < nchunks; c++) {
        const uint32_t asb = (c & 1) ? as1 : as0;
        const uint32_t bsb = (c & 1) ? bs1 : bs0;
        if (c + 1 < nchunks) {
            load_stage((c & 1) ? as0 : as1, (c & 1) ? bs0 : bs1, c + 1);
            cp_commit();
            cp_wait<1>();
        } else {
            cp_wait<0>();
        }
        __syncthreads();

        #pragma unroll
        for (int ks = 0; ks < 2; ks++) {
            uint32_t af[4][4], bf[2][4];
            #pragma unroll
            for (int fm = 0; fm < 4; fm++) {
                uint32_t addr = asb +
                    2u * ((wm0 + fm * 16 + a_lrow) * ASTR + ks * 16 + a_lcol);
                ldsm_x4(af[fm], addr);
            }
            #pragma unroll
            for (int p = 0; p < 2; p++) {
                uint32_t addr = bsb +
                    2u * ((ks * 16 + b_krow) * BSTR + wn0 + p * 16 + b_ncol);
                ldsm_x4_trans(bf[p], addr);
            }
            #pragma unroll
            for (int fm = 0; fm < 4; fm++)
                #pragma unroll
                for (int fn = 0; fn < 4; fn++)
                    mma16816(acc[fm][fn], af[fm],
                             bf[fn >> 1][(fn & 1) * 2],
                             bf[fn >> 1][(fn & 1) * 2 + 1]);
        }
        __syncthreads();
    }

    const int g = lane >> 2, t = lane & 3;
    #pragma unroll
    for (int fm = 0; fm < 4; fm++) {
        #pragma unroll
        for (int fn = 0; fn < 4; fn++) {
            int r = row0 + wm0 + fm * 16 + g;
            int cc = col0 + wn0 + fn * 8 + 2 * t;
            *(float2*)(C + (size_t)r * N + cc) =
                make_float2(acc[fm][fn][0], acc[fm][fn][1]);
            *(float2*)(C + (size_t)(r + 8) * N + cc) =
                make_float2(acc[fm][fn][2], acc[fm][fn][3]);
        }
    }
}

// ---------------------------------------------------------------------------
// RoPE + hi/lo split; V hi-only split.
// ---------------------------------------------------------------------------
__global__ void rope_split_kernel(const float* __restrict__ QKV,
                                  const float* __restrict__ cosT,
                                  const float* __restrict__ sinT,
                                  int nheads, int col0,
                                  __half* __restrict__ outH,
                                  __half* __restrict__ outL, int outw) {
    int idx = blockIdx.x * blockDim.x + threadIdx.x;
    int total = SEQ * nheads * 32;
    if (idx >= total) return;
    int i = idx % 32;
    int h = (idx / 32) % nheads;
    int s = idx / (32 * nheads);
    float c  = cosT[s * 32 + i];
    float sn = sinT[s * 32 + i];
    const float* row = QKV + (size_t)s * QKVN + col0 + h * HD;
    float t1 = row[i], t2 = row[i + 32];
    float r1 = t1 * c - t2 * sn;
    float r2 = t2 * c + t1 * sn;
    size_t o = (size_t)s * outw + h * HD + i;
    __half h1 = __float2half(r1);
    __half h2 = __float2half(r2);
    outH[o]      = h1;  outL[o]      = __float2half(r1 - __half2float(h1));
    outH[o + 32] = h2;  outL[o + 32] = __float2half(r2 - __half2float(h2));
}

__global__ void v_split_kernel(const float* __restrict__ QKV,
                               __half* __restrict__ Vh) {
    int idx = blockIdx.x * blockDim.x + threadIdx.x;
    if (idx >= SEQ * KVW) return;
    int s = idx / KVW, j = idx % KVW;
    Vh[idx] = __float2half(QKV[(size_t)s * QKVN + 1280 + j]);
}

// ---------------------------------------------------------------------------
// Tensor-core flash attention. 4 warps, BQ=64, BK=64.
// QK^T: 3-term hi/lo emulation. P·V: plain fp16 (error ~2.5e-4, within budget).
// ---------------------------------------------------------------------------
#define ATS 72
#define ATILE (64 * ATS)

__device__ __forceinline__ uint32_t pack_h2(float a, float b) {
    __half2 h = __floats2half2_rn(a, b);
    return *(uint32_t*)&h;
}

__global__ __launch_bounds__(128)
void attn_mma_kernel(const __half* __restrict__ Qh_, const __half* __restrict__ Ql_,
                     const __half* __restrict__ Kh_, const __half* __restrict__ Kl_,
                     const __half* __restrict__ Vh_,
                     __half* __restrict__ O) {
    extern __shared__ __half sm[];
    __half* QsH = sm;
    __half* QsL = sm + ATILE;
    __half* KsH = sm + 2 * ATILE;
    __half* KsL = sm + 3 * ATILE;
    __half* VsH = sm + 4 * ATILE;

    const int qt  = blockIdx.x;
    const int h   = blockIdx.y;
    const int kvh = h / (NH / NKV);
    const int tid = threadIdx.x;
    const int lane = tid & 31;
    const int wid = tid >> 5;

    const int lr = tid >> 1;
    const int lc = (tid & 1) * 32;

    {
        const __half* sh = Qh_ + (size_t)(qt * 64 + lr) * DMODEL + h * HD + lc;
        const __half* sl = Ql_ + (size_t)(qt * 64 + lr) * DMODEL + h * HD + lc;
        #pragma unroll
        for (int j = 0; j < 4; j++) {
            *(uint4*)(QsH + lr * ATS + lc + 8 * j) = *(const uint4*)(sh + 8 * j);
            *(uint4*)(QsL + lr * ATS + lc + 8 * j) = *(const uint4*)(sl + 8 * j);
        }
    }
    __syncthreads();

    const uint32_t qsh = smem_u32(QsH), qsl = smem_u32(QsL);
    const uint32_t ksh = smem_u32(KsH), ksl = smem_u32(KsL);
    const uint32_t vsh = smem_u32(VsH);

    const int a_lrow = lane & 15, a_lcol = (lane >> 4) << 3;
    const int b_noff = (lane & 7) + ((lane >> 4) << 3);
    const int b_koff = ((lane >> 3) & 1) << 3;

    uint32_t qfh[4][4], qfl[4][4];
    #pragma unroll
    for (int kk = 0; kk < 4; kk++) {
        uint32_t ao = 2u * ((wid * 16 + a_lrow) * ATS + kk * 16 + a_lcol);
        ldsm_x4(qfh[kk], qsh + ao);
        ldsm_x4(qfl[kk], qsl + ao);
    }

    const int g = lane >> 2, t = lane & 3;
    const int qg0 = qt * 64 + wid * 16 + g;
    const int qg1 = qg0 + 8;

    float o[8][4];
    #pragma unroll
    for (int nj = 0; nj < 8; nj++)
        #pragma unroll
        for (int e = 0; e < 4; e++) o[nj][e] = 0.f;
    float m0 = -INFINITY, m1 = -INFINITY, l0 = 0.f, l1 = 0.f;
    const float scale = 0.125f;

    for (int kt = 0; kt <= qt; kt++) {
        __syncthreads();
        {
            size_t gbase = (size_t)(kt * 64 + lr) * KVW + kvh * HD + lc;
            #pragma unroll
            for (int j = 0; j < 4; j++) {
                *(uint4*)(KsH + lr * ATS + lc + 8 * j) = *(const uint4*)(Kh_ + gbase + 8 * j);
                *(uint4*)(KsL + lr * ATS + lc + 8 * j) = *(const uint4*)(Kl_ + gbase + 8 * j);
                *(uint4*)(VsH + lr * ATS + lc + 8 * j) = *(const uint4*)(Vh_ + gbase + 8 * j);
            }
        }
        __syncthreads();

        // S = Q K^T (3-term hi/lo)
        float s[8][4];
        #pragma unroll
        for (int nj = 0; nj < 8; nj++)
            #pragma unroll
            for (int e = 0; e < 4; e++) s[nj][e] = 0.f;

        #pragma unroll
        for (int nj16 = 0; nj16 < 4; nj16++) {
            #pragma unroll
            for (int kk = 0; kk < 4; kk++) {
                uint32_t bo = 2u * ((nj16 * 16 + b_noff) * ATS + kk * 16 + b_koff);
                uint32_t bh[4], bl[4];
                ldsm_x4(bh, ksh + bo);
                ldsm_x4(bl, ksl + bo);
                mma16816(s[2 * nj16],     qfh[kk], bh[0], bh[1]);
                mma16816(s[2 * nj16],     qfl[kk], bh[0], bh[1]);
                mma16816(s[2 * nj16],     qfh[kk], bl[0], bl[1]);
                mma16816(s[2 * nj16 + 1], qfh[kk], bh[2], bh[3]);
                mma16816(s[2 * nj16 + 1], qfl[kk], bh[2], bh[3]);
                mma16816(s[2 * nj16 + 1], qfh[kk], bl[2], bl[3]);
            }
        }

        float mt0 = m0, mt1 = m1;
        const bool need_mask = (kt == qt);
        #pragma unroll
        for (int nj = 0; nj < 8; nj++) {
            int kg = kt * 64 + nj * 8 + 2 * t;
            #pragma unroll
            for (int e = 0; e < 4; e++) s[nj][e] *= scale;
            if (need_mask) {
                if (kg     > qg0) s[nj][0] = -INFINITY;
                if (kg + 1 > qg0) s[nj][1] = -INFINITY;
                if (kg     > qg1) s[nj][2] = -INFINITY;
                if (kg + 1 > qg1) s[nj][3] = -INFINITY;
            }
            mt0 = fmaxf(mt0, fmaxf(s[nj][0], s[nj][1]));
            mt1 = fmaxf(mt1, fmaxf(s[nj][2], s[nj][3]));
        }
        mt0 = fmaxf(mt0, __shfl_xor_sync(0xffffffffu, mt0, 1));
        mt0 = fmaxf(mt0, __shfl_xor_sync(0xffffffffu, mt0, 2));
        mt1 = fmaxf(mt1, __shfl_xor_sync(0xffffffffu, mt1, 1));
        mt1 = fmaxf(mt1, __shfl_xor_sync(0xffffffffu, mt1, 2));

        float corr0 = __expf(m0 - mt0);
        float corr1 = __expf(m1 - mt1);
        float ps0 = 0.f, ps1 = 0.f;
        #pragma unroll
        for (int nj = 0; nj < 8; nj++) {
            s[nj][0] = __expf(s[nj][0] - mt0);
            s[nj][1] = __expf(s[nj][1] - mt0);
            s[nj][2] = __expf(s[nj][2] - mt1);
            s[nj][3] = __expf(s[nj][3] - mt1);
            ps0 += s[nj][0] + s[nj][1];
            ps1 += s[nj][2] + s[nj][3];
        }
        ps0 += __shfl_xor_sync(0xffffffffu, ps0, 1);
        ps0 += __shfl_xor_sync(0xffffffffu, ps0, 2);
        ps1 += __shfl_xor_sync(0xffffffffu, ps1, 1);
        ps1 += __shfl_xor_sync(0xffffffffu, ps1, 2);
        l0 = l0 * corr0 + ps0;  m0 = mt0;
        l1 = l1 * corr1 + ps1;  m1 = mt1;

        #pragma unroll
        for (int nj = 0; nj < 8; nj++) {
            o[nj][0] *= corr0;  o[nj][1] *= corr0;
            o[nj][2] *= corr1;  o[nj][3] *= corr1;
        }

        // O += P V (fp16 P, fp16 V, fp32 accum)
        #pragma unroll
        for (int kk = 0; kk < 4; kk++) {
            uint32_t pah[4];
            pah[0] = pack_h2(s[2 * kk][0],     s[2 * kk][1]);
            pah[1] = pack_h2(s[2 * kk][2],     s[2 * kk][3]);
            pah[2] = pack_h2(s[2 * kk + 1][0], s[2 * kk + 1][1]);
            pah[3] = pack_h2(s[2 * kk + 1][2], s[2 * kk + 1][3]);
            #pragma unroll
            for (int dj16 = 0; dj16 < 4; dj16++) {
                uint32_t vo = 2u * ((kk * 16 + (lane & 15)) * ATS +
                                    dj16 * 16 + ((lane >> 4) << 3));
                uint32_t bh[4];
                ldsm_x4_trans(bh, vsh + vo);
                mma16816(o[2 * dj16],     pah, bh[0], bh[1]);
                mma16816(o[2 * dj16 + 1], pah, bh[2], bh[3]);
            }
        }
    }

    float inv0 = 1.f / l0, inv1 = 1.f / l1;
    #pragma unroll
    for (int nj = 0; nj < 8; nj++) {
        int col = h * HD + nj * 8 + 2 * t;
        __half2 v0 = __floats2half2_rn(o[nj][0] * inv0, o[nj][1] * inv0);
        __half2 v1 = __floats2half2_rn(o[nj][2] * inv1, o[nj][3] * inv1);
        *(__half2*)(O + (size_t)qg0 * DMODEL + col) = v0;
        *(__half2*)(O + (size_t)qg1 * DMODEL + col) = v1;
    }
}

// ---------------------------------------------------------------------------
// Launch. Inputs: x, rope_cos, rope_sin, Wq, Wk, Wv, Wo
// ---------------------------------------------------------------------------
extern "C" void kernel_launch(void* const* d_in, const int* in_sizes, int n_in,
                              void* d_out, int out_size) {
    const float* x    = (const float*)d_in[0];
    const float* cosT = (const float*)d_in[1];
    const float* sinT = (const float*)d_in[2];
    const float* Wq   = (const float*)d_in[3];
    const float* Wk   = (const float*)d_in[4];
    const float* Wv   = (const float*)d_in[5];
    const float* Wo   = (const float*)d_in[6];
    float* out = (float*)d_out;

    __half *x16, *wqkv16, *wo16, *o16, *qh, *ql, *kh, *kl, *vh;
    float *qkv;
    cudaGetSymbolAddress((void**)&x16,    g_x16);
    cudaGetSymbolAddress((void**)&wqkv16, g_Wqkv16);
    cudaGetSymbolAddress((void**)&wo16,   g_Wo16);
    cudaGetSymbolAddress((void**)&qkv,    g_QKV);
    cudaGetSymbolAddress((void**)&o16,    g_O16);
    cudaGetSymbolAddress((void**)&qh, g_Qh);  cudaGetSymbolAddress((void**)&ql, g_Ql);
    cudaGetSymbolAddress((void**)&kh, g_Kh);  cudaGetSymbolAddress((void**)&kl, g_Kl);
    cudaGetSymbolAddress((void**)&vh, g_Vh);

    const int attn_smem = 5 * ATILE * 2;   // 46080 bytes
    cudaFuncSetAttribute(attn_mma_kernel,
                         cudaFuncAttributeMaxDynamicSharedMemorySize, attn_smem);

    // Converts (x, fused Wqkv, Wo)
    {
        int n = SEQ * DMODEL;
        conv_f16_kernel<<<(n + 255) / 256, 256>>>(x, x16, n);
        int nw = DMODEL * QKVN;
        conv_wqkv_kernel<<<(nw + 255) / 256, 256>>>(Wq, Wk, Wv, wqkv16);
        int no = DMODEL * DMODEL;
        conv_f16_kernel<<<(no + 255) / 256, 256>>>(Wo, wo16, no);
    }

    // Fused QKV projection
    gemm_hmma_kernel<<<dim3(QKVN / BN, SEQ / BM), 256>>>(
        x16, wqkv16, qkv, SEQ, QKVN, DMODEL);

    // RoPE + splits
    {
        int totq = SEQ * NH * 32;
        rope_split_kernel<<<(totq + 255) / 256, 256>>>(
            qkv, cosT, sinT, NH, 0, qh, ql, DMODEL);
        int totk = SEQ * NKV * 32;
        rope_split_kernel<<<(totk + 255) / 256, 256>>>(
            qkv, cosT, sinT, NKV, 1024, kh, kl, KVW);
        int totv = SEQ * KVW;
        v_split_kernel<<<(totv + 255) / 256, 256>>>(qkv, vh);
    }

    // Tensor-core flash attention
    {
        dim3 grid(SEQ / 64, NH);
        attn_mma_kernel<<<grid, 128, attn_smem>>>(qh, ql, kh, kl, vh, o16);
    }

    // Output projection
    gemm_hmma_kernel<<<dim3(DMODEL / BN, SEQ / BM), 256>>>(
        o16, wo16, out, SEQ, DMODEL, DMODEL);
}